// round 4
// baseline (speedup 1.0000x reference)
#include <cuda_runtime.h>

// ConvTranspose2d-equivalent of the jax reference:
// out[co][oy][ox] = sum_{ci,ky,kx} x[ci][oy-ky][ox-kx] * w[co][ci][ky][kx]
//   (note: w axis 0 = OUTPUT channel for the passed array — verified against
//    jax.lax.conv_transpose(transpose_kernel=True, IOHW) semantics)
// x: [1, 64, 1024, 1024] fp32, w: [64, 64, 3, 3] fp32, out: [1, 64, 1026, 1026]

#define H     1024
#define W     1024
#define OH    1026
#define OW    1026
#define CIN   64
#define COUT  64

#define CO_BLK 16     // output channels per block
#define TOY    32     // output rows per block
#define TOX    64     // output cols per block
#define SXR    34     // smem x tile rows  (TOY + 2)
#define SXS    66     // smem x tile cols  (TOX + 2); stride 66 -> <=2-way LDS conflicts

__global__ __launch_bounds__(256, 1)
void convt_kernel(const float* __restrict__ x,
                  const float* __restrict__ wgt,
                  float* __restrict__ out)
{
    __shared__ __align__(16) float sw[CIN * 9 * CO_BLK];   // [ci][tap][co_local]  36 KB
    __shared__ float sx[SXR * SXS];                        // zero-padded x halo tile ~9 KB

    const int tid = threadIdx.x;
    const int ox0 = blockIdx.x * TOX;
    const int oy0 = blockIdx.y * TOY;
    const int co0 = blockIdx.z * CO_BLK;

    // Stage weights for this co-block: sw[ci*144 + tap*16 + c] = w[co0+c][ci][tap]
    for (int i = tid; i < CIN * 9 * CO_BLK; i += 256) {
        int c  = i & (CO_BLK - 1);
        int t  = (i >> 4) % 9;
        int ci = i / (9 * CO_BLK);
        sw[i] = wgt[((co0 + c) * CIN + ci) * 9 + t];
    }

    float acc[CO_BLK][8];
    #pragma unroll
    for (int c = 0; c < CO_BLK; c++)
        #pragma unroll
        for (int p = 0; p < 8; p++) acc[c][p] = 0.f;

    const int ty = tid >> 3;   // 0..31 : output row within tile
    const int tx = tid & 7;    // 0..7  : 8-pixel strip within 64-wide tile

    for (int ci = 0; ci < CIN; ci++) {
        __syncthreads();
        // Stage zero-padded x halo tile for this ci
        const float* xp = x + (size_t)ci * (H * W);
        for (int i = tid; i < SXR * SXS; i += 256) {
            int r  = i / SXS;
            int cc = i - r * SXS;
            int iy = oy0 - 2 + r;
            int ix = ox0 - 2 + cc;
            float v = 0.f;
            if ((unsigned)iy < (unsigned)H && (unsigned)ix < (unsigned)W)
                v = xp[iy * W + ix];
            sx[i] = v;
        }
        __syncthreads();

        const float* swc = sw + ci * (9 * CO_BLK);
        #pragma unroll
        for (int ky = 0; ky < 3; ky++) {
            // 10-wide x register window: serves all kx in 0..2, p in 0..7
            float xr[10];
            const float* rp = &sx[(ty + 2 - ky) * SXS + tx * 8];
            #pragma unroll
            for (int j = 0; j < 10; j++) xr[j] = rp[j];

            #pragma unroll
            for (int kx = 0; kx < 3; kx++) {
                // 16 weights, broadcast LDS.128 x4
                const float4* wv = (const float4*)(swc + (ky * 3 + kx) * CO_BLK);
                float wr[CO_BLK];
                #pragma unroll
                for (int q = 0; q < CO_BLK / 4; q++) {
                    float4 t4 = wv[q];
                    wr[q*4+0] = t4.x; wr[q*4+1] = t4.y;
                    wr[q*4+2] = t4.z; wr[q*4+3] = t4.w;
                }
                #pragma unroll
                for (int p = 0; p < 8; p++) {
                    float xv = xr[p + 2 - kx];
                    #pragma unroll
                    for (int c = 0; c < CO_BLK; c++)
                        acc[c][p] = fmaf(xv, wr[c], acc[c][p]);
                }
            }
        }
    }

    // Guarded float2 stores. OW=1026 even, oxb even -> pairs never straddle edge.
    const int oy  = oy0 + ty;
    const int oxb = ox0 + tx * 8;
    if (oy < OH) {
        #pragma unroll
        for (int c = 0; c < CO_BLK; c++) {
            float* op = out + ((size_t)(co0 + c) * OH + oy) * OW + oxb;
            #pragma unroll
            for (int p2 = 0; p2 < 4; p2++) {
                int ox = oxb + p2 * 2;
                if (ox < OW) {
                    float2 v = make_float2(acc[c][p2 * 2], acc[c][p2 * 2 + 1]);
                    *(float2*)(op + p2 * 2) = v;
                }
            }
        }
    }
}

extern "C" void kernel_launch(void* const* d_in, const int* in_sizes, int n_in,
                              void* d_out, int out_size)
{
    // Size-based dispatch as insurance against input ordering:
    // x has 64*1024*1024 = 67108864 elems, w has 64*64*9 = 36864.
    const float* x = (const float*)d_in[0];
    const float* w = (const float*)d_in[1];
    if (n_in >= 2 && in_sizes[0] < in_sizes[1]) {
        x = (const float*)d_in[1];
        w = (const float*)d_in[0];
    }
    float* out = (float*)d_out;

    dim3 grid((OW + TOX - 1) / TOX,   // 17
              (OH + TOY - 1) / TOY,   // 33
              COUT / CO_BLK);         // 4
    convt_kernel<<<grid, 256>>>(x, w, out);
}

// round 5
// speedup vs baseline: 1.0000x; 1.0000x over previous
#include <cuda_runtime.h>

// ConvTranspose2d-equivalent of the jax reference:
// out[co][oy][ox] = sum_{ci,ky,kx} x[ci][oy-ky][ox-kx] * w[co][ci][ky][kx]
//   (note: w axis 0 = OUTPUT channel for the passed array — verified against
//    jax.lax.conv_transpose(transpose_kernel=True, IOHW) semantics)
// x: [1, 64, 1024, 1024] fp32, w: [64, 64, 3, 3] fp32, out: [1, 64, 1026, 1026]

#define H     1024
#define W     1024
#define OH    1026
#define OW    1026
#define CIN   64
#define COUT  64

#define CO_BLK 16     // output channels per block
#define TOY    32     // output rows per block
#define TOX    64     // output cols per block
#define SXR    34     // smem x tile rows  (TOY + 2)
#define SXS    66     // smem x tile cols  (TOX + 2); stride 66 -> <=2-way LDS conflicts

__global__ __launch_bounds__(256, 1)
void convt_kernel(const float* __restrict__ x,
                  const float* __restrict__ wgt,
                  float* __restrict__ out)
{
    __shared__ __align__(16) float sw[CIN * 9 * CO_BLK];   // [ci][tap][co_local]  36 KB
    __shared__ float sx[SXR * SXS];                        // zero-padded x halo tile ~9 KB

    const int tid = threadIdx.x;
    const int ox0 = blockIdx.x * TOX;
    const int oy0 = blockIdx.y * TOY;
    const int co0 = blockIdx.z * CO_BLK;

    // Stage weights for this co-block: sw[ci*144 + tap*16 + c] = w[co0+c][ci][tap]
    for (int i = tid; i < CIN * 9 * CO_BLK; i += 256) {
        int c  = i & (CO_BLK - 1);
        int t  = (i >> 4) % 9;
        int ci = i / (9 * CO_BLK);
        sw[i] = wgt[((co0 + c) * CIN + ci) * 9 + t];
    }

    float acc[CO_BLK][8];
    #pragma unroll
    for (int c = 0; c < CO_BLK; c++)
        #pragma unroll
        for (int p = 0; p < 8; p++) acc[c][p] = 0.f;

    const int ty = tid >> 3;   // 0..31 : output row within tile
    const int tx = tid & 7;    // 0..7  : 8-pixel strip within 64-wide tile

    for (int ci = 0; ci < CIN; ci++) {
        __syncthreads();
        // Stage zero-padded x halo tile for this ci
        const float* xp = x + (size_t)ci * (H * W);
        for (int i = tid; i < SXR * SXS; i += 256) {
            int r  = i / SXS;
            int cc = i - r * SXS;
            int iy = oy0 - 2 + r;
            int ix = ox0 - 2 + cc;
            float v = 0.f;
            if ((unsigned)iy < (unsigned)H && (unsigned)ix < (unsigned)W)
                v = xp[iy * W + ix];
            sx[i] = v;
        }
        __syncthreads();

        const float* swc = sw + ci * (9 * CO_BLK);
        #pragma unroll
        for (int ky = 0; ky < 3; ky++) {
            // 10-wide x register window: serves all kx in 0..2, p in 0..7
            float xr[10];
            const float* rp = &sx[(ty + 2 - ky) * SXS + tx * 8];
            #pragma unroll
            for (int j = 0; j < 10; j++) xr[j] = rp[j];

            #pragma unroll
            for (int kx = 0; kx < 3; kx++) {
                // 16 weights, broadcast LDS.128 x4
                const float4* wv = (const float4*)(swc + (ky * 3 + kx) * CO_BLK);
                float wr[CO_BLK];
                #pragma unroll
                for (int q = 0; q < CO_BLK / 4; q++) {
                    float4 t4 = wv[q];
                    wr[q*4+0] = t4.x; wr[q*4+1] = t4.y;
                    wr[q*4+2] = t4.z; wr[q*4+3] = t4.w;
                }
                #pragma unroll
                for (int p = 0; p < 8; p++) {
                    float xv = xr[p + 2 - kx];
                    #pragma unroll
                    for (int c = 0; c < CO_BLK; c++)
                        acc[c][p] = fmaf(xv, wr[c], acc[c][p]);
                }
            }
        }
    }

    // Guarded float2 stores. OW=1026 even, oxb even -> pairs never straddle edge.
    const int oy  = oy0 + ty;
    const int oxb = ox0 + tx * 8;
    if (oy < OH) {
        #pragma unroll
        for (int c = 0; c < CO_BLK; c++) {
            float* op = out + ((size_t)(co0 + c) * OH + oy) * OW + oxb;
            #pragma unroll
            for (int p2 = 0; p2 < 4; p2++) {
                int ox = oxb + p2 * 2;
                if (ox < OW) {
                    float2 v = make_float2(acc[c][p2 * 2], acc[c][p2 * 2 + 1]);
                    *(float2*)(op + p2 * 2) = v;
                }
            }
        }
    }
}

extern "C" void kernel_launch(void* const* d_in, const int* in_sizes, int n_in,
                              void* d_out, int out_size)
{
    // Size-based dispatch as insurance against input ordering:
    // x has 64*1024*1024 = 67108864 elems, w has 64*64*9 = 36864.
    const float* x = (const float*)d_in[0];
    const float* w = (const float*)d_in[1];
    if (n_in >= 2 && in_sizes[0] < in_sizes[1]) {
        x = (const float*)d_in[1];
        w = (const float*)d_in[0];
    }
    float* out = (float*)d_out;

    dim3 grid((OW + TOX - 1) / TOX,   // 17
              (OH + TOY - 1) / TOY,   // 33
              COUT / CO_BLK);         // 4
    convt_kernel<<<grid, 256>>>(x, w, out);
}

// round 6
// speedup vs baseline: 1.5093x; 1.5092x over previous
#include <cuda_runtime.h>

// ConvTranspose2d-equivalent of the jax reference:
// out[co][oy][ox] = sum_{ci,ky,kx} x[ci][oy-ky][ox-kx] * w[co][ci][ky][kx]
// x: [1, 64, 1024, 1024] fp32, w: [64, 64, 3, 3] fp32, out: [1, 64, 1026, 1026]

#define H     1024
#define W     1024
#define OH    1026
#define OW    1026
#define CIN   64
#define COUT  64

#define CO_BLK 8      // output channels per block
#define TOY    32     // output rows per block
#define TOX    64     // output cols per block
#define SXR    34     // smem x tile rows  (TOY + 2)
#define SXS    66     // smem x tile cols  (TOX + 2); <=2-way LDS conflicts
#define SXN    (SXR * SXS)          // 2244
#define NSTG   ((SXN + 255) / 256)  // 9 staging elems per thread

__global__ __launch_bounds__(256, 2)
void convt_kernel(const float* __restrict__ x,
                  const float* __restrict__ wgt,
                  float* __restrict__ out)
{
    __shared__ __align__(16) float sw[CIN * 9 * CO_BLK]; // [ci][tap][co8]  18 KB
    __shared__ float sx[2][SXN];                         // double-buffered halo  18 KB

    const int tid = threadIdx.x;
    const int co0 = blockIdx.x * CO_BLK;   // co fastest -> x-tile L2 reuse
    const int ox0 = blockIdx.y * TOX;
    const int oy0 = blockIdx.z * TOY;

    // Stage weights: sw[ci*72 + tap*8 + c] = w[co0+c][ci][tap]
    for (int i = tid; i < CIN * 9 * CO_BLK; i += 256) {
        int c  = i & (CO_BLK - 1);
        int t  = (i >> 3) % 9;
        int ci = i / (9 * CO_BLK);
        sw[i] = wgt[((co0 + c) * CIN + ci) * 9 + t];
    }

    // Precompute per-thread staging offsets/validity (invariant across ci)
    int gofs[NSTG];
    unsigned vmask = 0;
    #pragma unroll
    for (int k = 0; k < NSTG; k++) {
        int i = tid + k * 256;
        if (i < SXN) {
            int r  = i / SXS;
            int cc = i - r * SXS;
            int iy = oy0 - 2 + r;
            int ix = ox0 - 2 + cc;
            if ((unsigned)iy < (unsigned)H && (unsigned)ix < (unsigned)W) {
                gofs[k] = iy * W + ix;
                vmask |= (1u << k);
            } else gofs[k] = 0;
        } else gofs[k] = 0;
    }

    float acc[CO_BLK][8];
    #pragma unroll
    for (int c = 0; c < CO_BLK; c++)
        #pragma unroll
        for (int p = 0; p < 8; p++) acc[c][p] = 0.f;

    const int ty = tid >> 3;   // 0..31 : output row within tile
    const int tx = tid & 7;    // 0..7  : 8-px strip within 64-wide tile

    // Prologue: stage ci=0 into buffer 0
    float ld[NSTG];
    {
        const float* xp = x;
        #pragma unroll
        for (int k = 0; k < NSTG; k++)
            ld[k] = (vmask >> k & 1) ? __ldg(xp + gofs[k]) : 0.f;
        #pragma unroll
        for (int k = 0; k < NSTG; k++) {
            int i = tid + k * 256;
            if (i < SXN) sx[0][i] = ld[k];
        }
    }
    __syncthreads();

    for (int ci = 0; ci < CIN; ci++) {
        const int cur = ci & 1;
        const bool more = (ci + 1 < CIN);

        // Prefetch next ci tile into registers (latency hidden under compute)
        if (more) {
            const float* xp = x + (size_t)(ci + 1) * (H * W);
            #pragma unroll
            for (int k = 0; k < NSTG; k++)
                ld[k] = (vmask >> k & 1) ? __ldg(xp + gofs[k]) : 0.f;
        }

        // Compute on current buffer
        const float* swc = sw + ci * (9 * CO_BLK);
        const float* sxc = sx[cur];
        #pragma unroll
        for (int ky = 0; ky < 3; ky++) {
            float xr[10];
            const float* rp = &sxc[(ty + 2 - ky) * SXS + tx * 8];
            #pragma unroll
            for (int j = 0; j < 10; j++) xr[j] = rp[j];

            #pragma unroll
            for (int kx = 0; kx < 3; kx++) {
                const float4* wv = (const float4*)(swc + (ky * 3 + kx) * CO_BLK);
                float4 w0 = wv[0], w1 = wv[1];
                float wr[CO_BLK] = {w0.x, w0.y, w0.z, w0.w, w1.x, w1.y, w1.z, w1.w};
                #pragma unroll
                for (int p = 0; p < 8; p++) {
                    float xv = xr[p + 2 - kx];
                    #pragma unroll
                    for (int c = 0; c < CO_BLK; c++)
                        acc[c][p] = fmaf(xv, wr[c], acc[c][p]);
                }
            }
        }

        // Drain prefetched tile into the other buffer
        if (more) {
            float* dst = sx[cur ^ 1];
            #pragma unroll
            for (int k = 0; k < NSTG; k++) {
                int i = tid + k * 256;
                if (i < SXN) dst[i] = ld[k];
            }
        }
        __syncthreads();
    }

    // Guarded float2 stores. OW=1026 even, oxb even -> pairs never straddle edge.
    const int oy  = oy0 + ty;
    const int oxb = ox0 + tx * 8;
    if (oy < OH) {
        #pragma unroll
        for (int c = 0; c < CO_BLK; c++) {
            float* op = out + ((size_t)(co0 + c) * OH + oy) * OW + oxb;
            #pragma unroll
            for (int p2 = 0; p2 < 4; p2++) {
                int ox = oxb + p2 * 2;
                if (ox < OW) {
                    float2 v = make_float2(acc[c][p2 * 2], acc[c][p2 * 2 + 1]);
                    *(float2*)(op + p2 * 2) = v;
                }
            }
        }
    }
}

extern "C" void kernel_launch(void* const* d_in, const int* in_sizes, int n_in,
                              void* d_out, int out_size)
{
    // Size-based input dispatch: x = 67.1M elems, w = 36.9K elems.
    const float* x = (const float*)d_in[0];
    const float* w = (const float*)d_in[1];
    if (n_in >= 2 && in_sizes[0] < in_sizes[1]) {
        x = (const float*)d_in[1];
        w = (const float*)d_in[0];
    }
    float* out = (float*)d_out;

    dim3 grid(COUT / CO_BLK,            // 8  (co fastest -> L2 reuse of x tiles)
              (OW + TOX - 1) / TOX,     // 17
              (OH + TOY - 1) / TOY);    // 33
    convt_kernel<<<grid, 256>>>(x, w, out);
}

// round 7
// speedup vs baseline: 1.5110x; 1.0011x over previous
#include <cuda_runtime.h>

// ConvTranspose2d-equivalent of the jax reference:
// out[co][oy][ox] = sum_{ci,ky,kx} x[ci][oy-ky][ox-kx] * w[co][ci][ky][kx]
// x: [1, 64, 1024, 1024] fp32, w: [64, 64, 3, 3] fp32, out: [1, 64, 1026, 1026]

#define H     1024
#define W     1024
#define OH    1026
#define OW    1026
#define CIN   64
#define COUT  64

#define CO_BLK 8      // output channels per block
#define TOY    32     // output rows per block
#define TOX    64     // output cols per block
#define SXR    34     // smem x tile rows  (TOY + 2)
#define SXS    66     // smem x tile cols  (TOX + 2); <=2-way LDS conflicts
#define SXN    (SXR * SXS)          // 2244
#define NSTG   ((SXN + 255) / 256)  // 9 staging elems per thread

__global__ __launch_bounds__(256, 2)
void convt_kernel(const float* __restrict__ x,
                  const float* __restrict__ wgt,
                  float* __restrict__ out)
{
    __shared__ __align__(16) float sw[CIN * 9 * CO_BLK]; // [ci][tap][co8]  18 KB
    __shared__ float sx[2][SXN];                         // double-buffered halo  18 KB

    const int tid = threadIdx.x;
    const int co0 = blockIdx.x * CO_BLK;   // co fastest -> x-tile L2 reuse
    const int ox0 = blockIdx.y * TOX;
    const int oy0 = blockIdx.z * TOY;

    // Stage weights: sw[ci*72 + tap*8 + c] = w[co0+c][ci][tap]
    for (int i = tid; i < CIN * 9 * CO_BLK; i += 256) {
        int c  = i & (CO_BLK - 1);
        int t  = (i >> 3) % 9;
        int ci = i / (9 * CO_BLK);
        sw[i] = wgt[((co0 + c) * CIN + ci) * 9 + t];
    }

    // Precompute per-thread staging offsets/validity (invariant across ci)
    int gofs[NSTG];
    unsigned vmask = 0;
    #pragma unroll
    for (int k = 0; k < NSTG; k++) {
        int i = tid + k * 256;
        if (i < SXN) {
            int r  = i / SXS;
            int cc = i - r * SXS;
            int iy = oy0 - 2 + r;
            int ix = ox0 - 2 + cc;
            if ((unsigned)iy < (unsigned)H && (unsigned)ix < (unsigned)W) {
                gofs[k] = iy * W + ix;
                vmask |= (1u << k);
            } else gofs[k] = 0;
        } else gofs[k] = 0;
    }

    float acc[CO_BLK][8];
    #pragma unroll
    for (int c = 0; c < CO_BLK; c++)
        #pragma unroll
        for (int p = 0; p < 8; p++) acc[c][p] = 0.f;

    const int ty = tid >> 3;   // 0..31 : output row within tile
    const int tx = tid & 7;    // 0..7  : 8-px strip within 64-wide tile

    // Prologue: stage ci=0 into buffer 0
    float ld[NSTG];
    {
        const float* xp = x;
        #pragma unroll
        for (int k = 0; k < NSTG; k++)
            ld[k] = (vmask >> k & 1) ? __ldg(xp + gofs[k]) : 0.f;
        #pragma unroll
        for (int k = 0; k < NSTG; k++) {
            int i = tid + k * 256;
            if (i < SXN) sx[0][i] = ld[k];
        }
    }
    __syncthreads();

    for (int ci = 0; ci < CIN; ci++) {
        const int cur = ci & 1;
        const bool more = (ci + 1 < CIN);

        // Prefetch next ci tile into registers (latency hidden under compute)
        if (more) {
            const float* xp = x + (size_t)(ci + 1) * (H * W);
            #pragma unroll
            for (int k = 0; k < NSTG; k++)
                ld[k] = (vmask >> k & 1) ? __ldg(xp + gofs[k]) : 0.f;
        }

        // Compute on current buffer
        const float* swc = sw + ci * (9 * CO_BLK);
        const float* sxc = sx[cur];
        #pragma unroll
        for (int ky = 0; ky < 3; ky++) {
            float xr[10];
            const float* rp = &sxc[(ty + 2 - ky) * SXS + tx * 8];
            #pragma unroll
            for (int j = 0; j < 10; j++) xr[j] = rp[j];

            #pragma unroll
            for (int kx = 0; kx < 3; kx++) {
                const float4* wv = (const float4*)(swc + (ky * 3 + kx) * CO_BLK);
                float4 w0 = wv[0], w1 = wv[1];
                float wr[CO_BLK] = {w0.x, w0.y, w0.z, w0.w, w1.x, w1.y, w1.z, w1.w};
                #pragma unroll
                for (int p = 0; p < 8; p++) {
                    float xv = xr[p + 2 - kx];
                    #pragma unroll
                    for (int c = 0; c < CO_BLK; c++)
                        acc[c][p] = fmaf(xv, wr[c], acc[c][p]);
                }
            }
        }

        // Drain prefetched tile into the other buffer
        if (more) {
            float* dst = sx[cur ^ 1];
            #pragma unroll
            for (int k = 0; k < NSTG; k++) {
                int i = tid + k * 256;
                if (i < SXN) dst[i] = ld[k];
            }
        }
        __syncthreads();
    }

    // Guarded float2 stores. OW=1026 even, oxb even -> pairs never straddle edge.
    const int oy  = oy0 + ty;
    const int oxb = ox0 + tx * 8;
    if (oy < OH) {
        #pragma unroll
        for (int c = 0; c < CO_BLK; c++) {
            float* op = out + ((size_t)(co0 + c) * OH + oy) * OW + oxb;
            #pragma unroll
            for (int p2 = 0; p2 < 4; p2++) {
                int ox = oxb + p2 * 2;
                if (ox < OW) {
                    float2 v = make_float2(acc[c][p2 * 2], acc[c][p2 * 2 + 1]);
                    *(float2*)(op + p2 * 2) = v;
                }
            }
        }
    }
}

extern "C" void kernel_launch(void* const* d_in, const int* in_sizes, int n_in,
                              void* d_out, int out_size)
{
    // Size-based input dispatch: x = 67.1M elems, w = 36.9K elems.
    const float* x = (const float*)d_in[0];
    const float* w = (const float*)d_in[1];
    if (n_in >= 2 && in_sizes[0] < in_sizes[1]) {
        x = (const float*)d_in[1];
        w = (const float*)d_in[0];
    }
    float* out = (float*)d_out;

    dim3 grid(COUT / CO_BLK,            // 8  (co fastest -> L2 reuse of x tiles)
              (OW + TOX - 1) / TOX,     // 17
              (OH + TOY - 1) / TOY);    // 33
    convt_kernel<<<grid, 256>>>(x, w, out);
}

// round 8
// speedup vs baseline: 1.6411x; 1.0861x over previous
#include <cuda_runtime.h>
#include <cstdint>

// ConvTranspose2d-equivalent of the jax reference:
// out[co][oy][ox] = sum_{ci,ky,kx} x[ci][oy-ky][ox-kx] * w[co][ci][ky][kx]
// x: [1, 64, 1024, 1024] fp32, w: [64, 64, 3, 3] fp32, out: [1, 64, 1026, 1026]
//
// Compute uses packed fma.rn.f32x2 (FFMA2): each accumulator is a pixel pair.

#define H     1024
#define W     1024
#define OH    1026
#define OW    1026
#define CIN   64
#define COUT  64

#define CO_BLK 8      // output channels per block
#define TOY    32     // output rows per block
#define TOX    64     // output cols per block
#define SXR    34     // smem x tile rows  (TOY + 2)
#define SXS    66     // smem x tile cols  (TOX + 2); even stride -> 8B-aligned pairs
#define SXN    (SXR * SXS)          // 2244
#define NSTG   ((SXN + 255) / 256)  // 9 staging elems per thread

// d = a * b + d, element-wise on packed f32x2 (low = .x, high = .y)
#define FMA2(d, a, b) \
    asm("fma.rn.f32x2 %0, %1, %2, %0;" : "+l"(d) : "l"(a), "l"(b))
// pack two f32 bit-patterns into f32x2 (lo -> bits[0:32))
#define PACK2(o, lo, hi) \
    asm("mov.b64 %0, {%1, %2};" : "=l"(o) : "r"(lo), "r"(hi))

__global__ __launch_bounds__(256, 2)
void convt_kernel(const float* __restrict__ x,
                  const float* __restrict__ wgt,
                  float* __restrict__ out)
{
    __shared__ __align__(16) float sw[CIN * 9 * CO_BLK]; // [ci][tap][co8]  18 KB
    __shared__ float sx[2][SXN];                         // double-buffered halo 18 KB

    const int tid = threadIdx.x;
    const int co0 = blockIdx.x * CO_BLK;   // co fastest -> x-tile L2 reuse
    const int ox0 = blockIdx.y * TOX;
    const int oy0 = blockIdx.z * TOY;

    // Stage weights: sw[ci*72 + tap*8 + c] = w[co0+c][ci][tap]
    for (int i = tid; i < CIN * 9 * CO_BLK; i += 256) {
        int c  = i & (CO_BLK - 1);
        int t  = (i >> 3) % 9;
        int ci = i / (9 * CO_BLK);
        sw[i] = wgt[((co0 + c) * CIN + ci) * 9 + t];
    }

    // Per-thread staging offsets/validity (invariant across ci)
    int gofs[NSTG];
    unsigned vmask = 0;
    #pragma unroll
    for (int k = 0; k < NSTG; k++) {
        int i = tid + k * 256;
        gofs[k] = 0;
        if (i < SXN) {
            int r  = i / SXS;
            int cc = i - r * SXS;
            int iy = oy0 - 2 + r;
            int ix = ox0 - 2 + cc;
            if ((unsigned)iy < (unsigned)H && (unsigned)ix < (unsigned)W) {
                gofs[k] = iy * W + ix;
                vmask |= (1u << k);
            }
        }
    }

    // Packed accumulators: acc[c][p2] holds output pixels (2*p2, 2*p2+1)
    unsigned long long acc[CO_BLK][4];
    #pragma unroll
    for (int c = 0; c < CO_BLK; c++)
        #pragma unroll
        for (int p = 0; p < 4; p++) acc[c][p] = 0ull;

    const int ty = tid >> 3;   // 0..31 : output row within tile
    const int tx = tid & 7;    // 0..7  : 8-px strip within 64-wide tile

    // Prologue: stage ci=0 into buffer 0
    float ld[NSTG];
    {
        #pragma unroll
        for (int k = 0; k < NSTG; k++)
            ld[k] = (vmask >> k & 1) ? __ldg(x + gofs[k]) : 0.f;
        #pragma unroll
        for (int k = 0; k < NSTG; k++) {
            int i = tid + k * 256;
            if (i < SXN) sx[0][i] = ld[k];
        }
    }
    __syncthreads();

    for (int ci = 0; ci < CIN; ci++) {
        const int cur = ci & 1;
        const bool more = (ci + 1 < CIN);

        // Prefetch next ci tile into registers (hidden under compute)
        if (more) {
            const float* xp = x + (size_t)(ci + 1) * (H * W);
            #pragma unroll
            for (int k = 0; k < NSTG; k++)
                ld[k] = (vmask >> k & 1) ? __ldg(xp + gofs[k]) : 0.f;
        }

        const float* swc = sw + ci * (9 * CO_BLK);
        const float* sxc = sx[cur];
        #pragma unroll
        for (int ky = 0; ky < 3; ky++) {
            // 10-wide x register window serves all kx shifts
            float xr[10];
            const float* rp = &sxc[(ty + 2 - ky) * SXS + tx * 8];
            #pragma unroll
            for (int j = 0; j < 10; j++) xr[j] = rp[j];

            // even pairs pe[k] = (xr[2k], xr[2k+1]) reused by kx = 0 and 2
            unsigned long long pe[5];
            #pragma unroll
            for (int k = 0; k < 5; k++)
                PACK2(pe[k], __float_as_uint(xr[2 * k]), __float_as_uint(xr[2 * k + 1]));

            #pragma unroll
            for (int kx = 0; kx < 3; kx++) {
                // 8 lane-duplicated weight pairs for this tap
                const float4* wv = (const float4*)(swc + (ky * 3 + kx) * CO_BLK);
                float4 w0 = wv[0], w1 = wv[1];
                float wf[CO_BLK] = {w0.x, w0.y, w0.z, w0.w, w1.x, w1.y, w1.z, w1.w};
                unsigned long long wp[CO_BLK];
                #pragma unroll
                for (int c = 0; c < CO_BLK; c++) {
                    unsigned wb = __float_as_uint(wf[c]);
                    PACK2(wp[c], wb, wb);
                }

                // x pair for acc pair p2 at shift s=2-kx: (xr[2p2+s], xr[2p2+1+s])
                unsigned long long xp2[4];
                if (kx == 1) {            // odd shift: transient packs
                    #pragma unroll
                    for (int p = 0; p < 4; p++)
                        PACK2(xp2[p], __float_as_uint(xr[2 * p + 1]),
                                      __float_as_uint(xr[2 * p + 2]));
                } else {
                    const int b = (kx == 0) ? 1 : 0;   // s=2 -> pe[p+1], s=0 -> pe[p]
                    #pragma unroll
                    for (int p = 0; p < 4; p++) xp2[p] = pe[p + b];
                }

                #pragma unroll
                for (int p = 0; p < 4; p++)
                    #pragma unroll
                    for (int c = 0; c < CO_BLK; c++)
                        FMA2(acc[c][p], xp2[p], wp[c]);
            }
        }

        // Drain prefetched tile into the other buffer
        if (more) {
            float* dst = sx[cur ^ 1];
            #pragma unroll
            for (int k = 0; k < NSTG; k++) {
                int i = tid + k * 256;
                if (i < SXN) dst[i] = ld[k];
            }
        }
        __syncthreads();
    }

    // Guarded 8B stores: acc pair IS the float2. OW=1026 even, oxb even ->
    // pairs never straddle the right edge; 8B alignment holds (even index).
    const int oy  = oy0 + ty;
    const int oxb = ox0 + tx * 8;
    if (oy < OH) {
        #pragma unroll
        for (int c = 0; c < CO_BLK; c++) {
            float* op = out + ((size_t)(co0 + c) * OH + oy) * OW + oxb;
            #pragma unroll
            for (int p2 = 0; p2 < 4; p2++) {
                int ox = oxb + p2 * 2;
                if (ox < OW)
                    *(unsigned long long*)(op + p2 * 2) = acc[c][p2];
            }
        }
    }
}

extern "C" void kernel_launch(void* const* d_in, const int* in_sizes, int n_in,
                              void* d_out, int out_size)
{
    // Size-based input dispatch: x = 67.1M elems, w = 36.9K elems.
    const float* x = (const float*)d_in[0];
    const float* w = (const float*)d_in[1];
    if (n_in >= 2 && in_sizes[0] < in_sizes[1]) {
        x = (const float*)d_in[1];
        w = (const float*)d_in[0];
    }
    float* out = (float*)d_out;

    dim3 grid(COUT / CO_BLK,            // 8  (co fastest -> L2 reuse of x tiles)
              (OW + TOX - 1) / TOX,     // 17
              (OH + TOY - 1) / TOY);    // 33
    convt_kernel<<<grid, 256>>>(x, w, out);
}

// round 12
// speedup vs baseline: 3.7333x; 2.2748x over previous
#include <cuda_runtime.h>
#include <cuda_bf16.h>
#include <cstdint>

// ConvTranspose2d(64,64,k=3,s=1,p=0) fp32 via mma.sync bf16-split implicit GEMM.
// out[co][oy][ox] = sum_{ci,ky,kx} x[ci][oy-ky][ox-kx] * w[co][ci][ky][kx]
// (tcgen05 unavailable: harness compiles PTX at compute_103 (no 'a').
//  mma.sync.m16n8k16 + ldmatrix are baseline features and do compile.)

#define HH    1024
#define WW    1024
#define OHH   1026
#define OWW   1026
#define CIN   64
#define COUT  64

// scratch: pixel-major bf16 hi/lo split of x  (device globals, no alloc APIs)
__device__ __nv_bfloat16 g_xt_hi[(size_t)HH * WW * CIN];
__device__ __nv_bfloat16 g_xt_lo[(size_t)HH * WW * CIN];

// ---------------- helpers ----------------
__device__ __forceinline__ uint32_t smem_u32(const void* p) {
    uint32_t a;
    asm("{ .reg .u64 t; cvta.to.shared.u64 t, %1; cvt.u32.u64 %0, t; }" : "=r"(a) : "l"(p));
    return a;
}
__device__ __forceinline__ void ldsm4(uint32_t r[4], uint32_t addr) {
    asm volatile("ldmatrix.sync.aligned.m8n8.x4.shared.b16 {%0,%1,%2,%3}, [%4];"
        : "=r"(r[0]), "=r"(r[1]), "=r"(r[2]), "=r"(r[3]) : "r"(addr));
}
__device__ __forceinline__ uint32_t lds32(uint32_t a) {
    uint32_t v;
    asm volatile("ld.shared.b32 %0, [%1];" : "=r"(v) : "r"(a));
    return v;
}
__device__ __forceinline__ void mma16816(float d[4], const uint32_t a[4], const uint32_t b[2]) {
    asm volatile("mma.sync.aligned.m16n8k16.row.col.f32.bf16.bf16.f32 "
        "{%0,%1,%2,%3}, {%4,%5,%6,%7}, {%8,%9}, {%0,%1,%2,%3};"
        : "+f"(d[0]), "+f"(d[1]), "+f"(d[2]), "+f"(d[3])
        : "r"(a[0]), "r"(a[1]), "r"(a[2]), "r"(a[3]), "r"(b[0]), "r"(b[1]));
}

// ---------------- Kernel 1: transpose + hi/lo split ----------------
__global__ __launch_bounds__(256)
void prepass_kernel(const float* __restrict__ x)
{
    __shared__ float t[CIN * 33];
    const int tid = threadIdx.x;
    const int px0 = blockIdx.x * 32;
    const int y   = blockIdx.y;

    for (int i = tid; i < CIN * 32; i += 256) {
        int ci = i >> 5, j = i & 31;
        t[ci * 33 + j] = x[(size_t)ci * (HH * WW) + (size_t)y * WW + px0 + j];
    }
    __syncthreads();
    {
        int px = tid >> 3, c = tid & 7;
        __align__(16) __nv_bfloat16 h8[8], l8[8];
        #pragma unroll
        for (int k = 0; k < 8; k++) {
            float v = t[(c * 8 + k) * 33 + px];
            __nv_bfloat16 h = __float2bfloat16(v);
            h8[k] = h;
            l8[k] = __float2bfloat16(v - __bfloat162float(h));
        }
        size_t o = ((size_t)y * WW + px0 + px) * CIN + c * 8;
        *(uint4*)&g_xt_hi[o] = *(const uint4*)h8;
        *(uint4*)&g_xt_lo[o] = *(const uint4*)l8;
    }
}

// ---------------- Kernel 2: mma.sync main ----------------
// smem map (bytes):
//   A ring: 3 slots x {hi,lo} x 132 px-rows x 128B (16B-chunk XOR swizzle)
//   B:      [tap 9][sp 2][co 32][128B ci]  (chunk swizzle by co&7)
//   scratch: 32 co x 132 px f32 (epilogue transpose)
#define ASLOT  (132 * 128)                 // 16896
#define OFF_B  (6 * ASLOT)                 // 101376
#define OFF_S  (OFF_B + 18 * 4096)        // 175104
#define SMEM_SZ (OFF_S + 32 * 132 * 4)     // 192000
#define BAND   27

__device__ __forceinline__ void stage_row(char* smem, int y, int ox0, int tid)
{
    const int slot = (unsigned)(y + 6) % 3;
    char* ah = smem + slot * ASLOT;
    char* al = smem + (3 + slot) * ASLOT;
    const bool yv = (unsigned)y < (unsigned)HH;
    #pragma unroll
    for (int k = 0; k < 5; k++) {
        int i = tid + k * 256;
        if (i < 132 * 8) {
            int px = i >> 3, c = i & 7;
            int gx = ox0 - 2 + px;
            uint4 vh = make_uint4(0, 0, 0, 0), vl = vh;
            if (yv && (unsigned)gx < (unsigned)WW) {
                size_t o = ((size_t)y * WW + gx) * CIN + c * 8;
                vh = *(const uint4*)&g_xt_hi[o];
                vl = *(const uint4*)&g_xt_lo[o];
            }
            uint32_t so = (uint32_t)(px * 128 + ((c ^ (px & 7)) << 4));
            *(uint4*)(ah + so) = vh;
            *(uint4*)(al + so) = vl;
        }
    }
}

__global__ __launch_bounds__(256, 1)
void convt_mma_kernel(const float* __restrict__ wgt, float* __restrict__ out)
{
    extern __shared__ char smem[];
    const uint32_t sb = smem_u32(smem);
    const int tid = threadIdx.x;
    const int wid = tid >> 5, lid = tid & 31;

    const int co0 = blockIdx.x * 32;
    const int ox0 = blockIdx.y * 128;
    const int oy0 = blockIdx.z * BAND;

    // Stage weights: B[tap][sp][co][ci] bf16, chunk-swizzled rows of 128B
    for (int i = tid; i < 9 * 32 * CIN; i += 256) {
        int ci = i & 63, co = (i >> 6) & 31, tap = i >> 11;
        float v = wgt[((size_t)(co0 + co) * CIN + ci) * 9 + tap];
        __nv_bfloat16 h = __float2bfloat16(v);
        __nv_bfloat16 l = __float2bfloat16(v - __bfloat162float(h));
        uint32_t boff = (uint32_t)(co * 128 + (((ci >> 3) ^ (co & 7)) << 4) + ((ci & 7) << 1));
        *(__nv_bfloat16*)(smem + OFF_B + (tap * 2 + 0) * 4096 + boff) = h;
        *(__nv_bfloat16*)(smem + OFF_B + (tap * 2 + 1) * 4096 + boff) = l;
    }

    // Prologue rows
    stage_row(smem, oy0 - 2, ox0, tid);
    stage_row(smem, oy0 - 1, ox0, tid);

    const int j0 = (wid & 3) * 32;   // warp's px base  (2 m-tiles of 16)
    const int n0 = (wid >> 2) * 16;  // warp's co base  (2 n-tiles of 8)

    for (int it = 0; it < BAND; it++) {
        const int oy = oy0 + it;
        stage_row(smem, oy, ox0, tid);
        __syncthreads();

        float acc[2][2][4];
        #pragma unroll
        for (int m = 0; m < 2; m++)
            #pragma unroll
            for (int n = 0; n < 2; n++)
                #pragma unroll
                for (int q = 0; q < 4; q++) acc[m][n][q] = 0.f;

        #pragma unroll
        for (int ky = 0; ky < 3; ky++) {
            const int slot = (unsigned)(oy - ky + 6) % 3;
            const uint32_t ahb = sb + slot * ASLOT;
            const uint32_t alb = ahb + 3 * ASLOT;
            #pragma unroll
            for (int kx = 0; kx < 3; kx++) {
                const int s = 2 - kx;
                const uint32_t bhb = sb + OFF_B + ((ky * 3 + kx) * 2) * 4096;
                const uint32_t blb = bhb + 4096;
                #pragma unroll
                for (int k4 = 0; k4 < 4; k4++) {
                    uint32_t ah[2][4], al[2][4];
                    #pragma unroll
                    for (int mt = 0; mt < 2; mt++) {
                        int row = j0 + mt * 16 + s + (lid & 7) + ((lid >> 3) & 1) * 8;
                        int ch  = 2 * k4 + (lid >> 4);
                        uint32_t off = (uint32_t)(row * 128 + ((ch ^ (row & 7)) << 4));
                        ldsm4(ah[mt], ahb + off);
                        ldsm4(al[mt], alb + off);
                    }
                    uint32_t bh[2][2], bl[2][2];
                    #pragma unroll
                    for (int nt = 0; nt < 2; nt++) {
                        int co  = n0 + nt * 8 + (lid >> 2);
                        int ci0 = 16 * k4 + 2 * (lid & 3);
                        uint32_t base = (uint32_t)(co * 128 + ((ci0 & 7) << 1));
                        uint32_t o0 = base + ((((ci0 >> 3)    ) ^ (co & 7)) << 4);
                        uint32_t o1 = base + ((((ci0 >> 3) + 1) ^ (co & 7)) << 4);
                        bh[nt][0] = lds32(bhb + o0);  bh[nt][1] = lds32(bhb + o1);
                        bl[nt][0] = lds32(blb + o0);  bl[nt][1] = lds32(blb + o1);
                    }
                    #pragma unroll
                    for (int mt = 0; mt < 2; mt++)
                        #pragma unroll
                        for (int nt = 0; nt < 2; nt++) {
                            mma16816(acc[mt][nt], ah[mt], bh[nt]);  // xh*wh
                            mma16816(acc[mt][nt], ah[mt], bl[nt]);  // xh*wl
                            mma16816(acc[mt][nt], al[mt], bh[nt]);  // xl*wh
                        }
                }
            }
        }

        // Epilogue: fragments -> smem scratch [co][px] -> coalesced STG
        float* sout = (float*)(smem + OFF_S);
        #pragma unroll
        for (int mt = 0; mt < 2; mt++)
            #pragma unroll
            for (int nt = 0; nt < 2; nt++) {
                int px = j0 + mt * 16 + (lid >> 2);
                int co = n0 + nt * 8 + 2 * (lid & 3);
                sout[co * 132 + px]           = acc[mt][nt][0];
                sout[(co + 1) * 132 + px]     = acc[mt][nt][1];
                sout[co * 132 + px + 8]       = acc[mt][nt][2];
                sout[(co + 1) * 132 + px + 8] = acc[mt][nt][3];
            }
        __syncthreads();
        {
            int px = tid & 127;
            int half = tid >> 7;
            int ox = ox0 + px;
            if (ox < OWW) {
                #pragma unroll
                for (int r = 0; r < 16; r++) {
                    int col = half * 16 + r;
                    out[((size_t)(co0 + col) * OHH + oy) * OWW + ox] = sout[col * 132 + px];
                }
            }
        }
        __syncthreads();
    }
}

// ---------------- launch ----------------
extern "C" void kernel_launch(void* const* d_in, const int* in_sizes, int n_in,
                              void* d_out, int out_size)
{
    const float* x = (const float*)d_in[0];
    const float* w = (const float*)d_in[1];
    if (n_in >= 2 && in_sizes[0] < in_sizes[1]) {
        x = (const float*)d_in[1];
        w = (const float*)d_in[0];
    }
    float* out = (float*)d_out;

    cudaFuncSetAttribute(convt_mma_kernel,
                         cudaFuncAttributeMaxDynamicSharedMemorySize, SMEM_SZ);

    prepass_kernel<<<dim3(WW / 32, HH), 256>>>(x);
    // grid: 2 co-halves x 9 px-tiles x 38 bands of 27 rows (38*27 = 1026)
    convt_mma_kernel<<<dim3(COUT / 32, 9, OHH / BAND), 256, SMEM_SZ>>>(w, out);
}

// round 14
// speedup vs baseline: 3.8179x; 1.0227x over previous
#include <cuda_runtime.h>
#include <cuda_bf16.h>
#include <cstdint>

// ConvTranspose2d(64,64,k=3,s=1,p=0) fp32 via mma.sync bf16-split implicit GEMM.
// out[co][oy][ox] = sum_{ci,ky,kx} x[ci][oy-ky][ox-kx] * w[co][ci][ky][kx]

#define HH    1024
#define WW    1024
#define OHH   1026
#define OWW   1026
#define CIN   64
#define COUT  64

// scratch: pixel-major bf16 hi/lo split of x (device globals; no alloc APIs)
__device__ __nv_bfloat16 g_xt_hi[(size_t)HH * WW * CIN];
__device__ __nv_bfloat16 g_xt_lo[(size_t)HH * WW * CIN];

// ---------------- helpers ----------------
__device__ __forceinline__ uint32_t smem_u32(const void* p) {
    uint32_t a;
    asm("{ .reg .u64 t; cvta.to.shared.u64 t, %1; cvt.u32.u64 %0, t; }" : "=r"(a) : "l"(p));
    return a;
}
__device__ __forceinline__ void ldsm4(uint32_t r[4], uint32_t addr) {
    asm volatile("ldmatrix.sync.aligned.m8n8.x4.shared.b16 {%0,%1,%2,%3}, [%4];"
        : "=r"(r[0]), "=r"(r[1]), "=r"(r[2]), "=r"(r[3]) : "r"(addr));
}
__device__ __forceinline__ void mma16816(float d[4], const uint32_t a[4], const uint32_t b[2]) {
    asm volatile("mma.sync.aligned.m16n8k16.row.col.f32.bf16.bf16.f32 "
        "{%0,%1,%2,%3}, {%4,%5,%6,%7}, {%8,%9}, {%0,%1,%2,%3};"
        : "+f"(d[0]), "+f"(d[1]), "+f"(d[2]), "+f"(d[3])
        : "r"(a[0]), "r"(a[1]), "r"(a[2]), "r"(a[3]), "r"(b[0]), "r"(b[1]));
}

// ---------------- Kernel 1: transpose + hi/lo split (64-px tiles) ----------------
__global__ __launch_bounds__(512)
void prepass_kernel(const float* __restrict__ x)
{
    __shared__ float t[CIN * 65];
    const int tid = threadIdx.x;
    const int px0 = blockIdx.x * 64;
    const int y   = blockIdx.y;

    for (int i = tid; i < CIN * 64; i += 512) {
        int ci = i >> 6, j = i & 63;
        t[ci * 65 + j] = x[(size_t)ci * (HH * WW) + (size_t)y * WW + px0 + j];
    }
    __syncthreads();
    {
        int px = tid >> 3, c = tid & 7;
        __align__(16) __nv_bfloat16 h8[8], l8[8];
        #pragma unroll
        for (int k = 0; k < 8; k++) {
            float v = t[(c * 8 + k) * 65 + px];
            __nv_bfloat16 h = __float2bfloat16(v);
            h8[k] = h;
            l8[k] = __float2bfloat16(v - __bfloat162float(h));
        }
        size_t o = ((size_t)y * WW + px0 + px) * CIN + c * 8;
        *(uint4*)&g_xt_hi[o] = *(const uint4*)h8;
        *(uint4*)&g_xt_lo[o] = *(const uint4*)l8;
    }
}

// ---------------- Kernel 2: mma.sync main ----------------
// smem: A ring 4 slots x {hi,lo} x 132 px-rows x 128B (16B-chunk XOR swizzle),
//       B [tap 9][sp 2][co 32][128B ci] (chunk swizzle by co&7). No scratch.
#define ROWB   (132 * 128)                 // 16896 (one split-plane of one slot)
#define ASLOT2 (2 * ROWB)                  // 33792 (hi+lo per slot)
#define OFF_B  (4 * ASLOT2)                // 135168
#define SMEM_SZ (OFF_B + 18 * 4096)        // 208896
#define BAND   27

__device__ __forceinline__ void stage_row(char* smem, int y, int ox0, int tid)
{
    const int slot = (y + 8) & 3;
    char* ah = smem + slot * ASLOT2;
    char* al = ah + ROWB;
    const bool yv = (unsigned)y < (unsigned)HH;
    #pragma unroll
    for (int k = 0; k < 5; k++) {
        int i = tid + k * 256;
        if (i < 132 * 8) {
            int px = i >> 3, c = i & 7;
            int gx = ox0 - 2 + px;
            uint4 vh = make_uint4(0, 0, 0, 0), vl = vh;
            if (yv && (unsigned)gx < (unsigned)WW) {
                size_t o = ((size_t)y * WW + gx) * CIN + c * 8;
                vh = *(const uint4*)&g_xt_hi[o];
                vl = *(const uint4*)&g_xt_lo[o];
            }
            uint32_t so = (uint32_t)(px * 128 + ((c ^ (px & 7)) << 4));
            *(uint4*)(ah + so) = vh;
            *(uint4*)(al + so) = vl;
        }
    }
}

__global__ __launch_bounds__(256, 1)
void convt_mma_kernel(const float* __restrict__ wgt, float* __restrict__ out)
{
    extern __shared__ char smem[];
    const uint32_t sb = smem_u32(smem);
    const int tid = threadIdx.x;
    const int wid = tid >> 5, lid = tid & 31;

    const int co0 = blockIdx.x * 32;
    const int ox0 = blockIdx.y * 128;
    const int oy0 = blockIdx.z * BAND;

    // Stage weights: B[tap][sp][co][ci] bf16, chunk-swizzled 128B rows
    for (int i = tid; i < 9 * 32 * CIN; i += 256) {
        int ci = i & 63, co = (i >> 6) & 31, tap = i >> 11;
        float v = wgt[((size_t)(co0 + co) * CIN + ci) * 9 + tap];
        __nv_bfloat16 h = __float2bfloat16(v);
        __nv_bfloat16 l = __float2bfloat16(v - __bfloat162float(h));
        uint32_t boff = (uint32_t)(co * 128 + (((ci >> 3) ^ (co & 7)) << 4) + ((ci & 7) << 1));
        *(__nv_bfloat16*)(smem + OFF_B + (tap * 2 + 0) * 4096 + boff) = h;
        *(__nv_bfloat16*)(smem + OFF_B + (tap * 2 + 1) * 4096 + boff) = l;
    }

    // Prologue rows
    stage_row(smem, oy0 - 2, ox0, tid);
    stage_row(smem, oy0 - 1, ox0, tid);
    stage_row(smem, oy0,     ox0, tid);

    const int j0 = (wid & 3) * 32;   // warp px base (2 m-tiles of 16)
    const int n0 = (wid >> 2) * 16;  // warp co base (2 n-tiles of 8)

    // per-lane invariants
    const int arow = (lid & 7) + ((lid >> 3) & 1) * 8;   // A ldsm row-in-tile
    const int ach  = lid >> 4;                           // A k-half select
    const int bm   = lid >> 3;                           // B ldsm matrix id
    const int brow = n0 + ((bm >> 1) << 3) + (lid & 7);  // B co row
    const int bch  = bm & 1;                             // B k-half select

    for (int it = 0; it < BAND; it++) {
        const int oy = oy0 + it;
        __syncthreads();                  // prev compute done; row oy visible
        if (it + 1 < BAND)                // prefetch next row into free slot
            stage_row(smem, oy + 1, ox0, tid);

        float acc[2][2][4];
        #pragma unroll
        for (int m = 0; m < 2; m++)
            #pragma unroll
            for (int n = 0; n < 2; n++)
                #pragma unroll
                for (int q = 0; q < 4; q++) acc[m][n][q] = 0.f;

        #pragma unroll
        for (int ky = 0; ky < 3; ky++) {
            const int slot = (oy - ky + 8) & 3;
            const uint32_t ahb = sb + slot * ASLOT2;
            const uint32_t alb = ahb + ROWB;
            #pragma unroll
            for (int kx = 0; kx < 3; kx++) {
                const int s = 2 - kx;
                const uint32_t bhb = sb + OFF_B + ((ky * 3 + kx) * 2) * 4096;
                #pragma unroll
                for (int k4 = 0; k4 < 4; k4++) {
                    uint32_t ah[2][4], al[2][4];
                    #pragma unroll
                    for (int mt = 0; mt < 2; mt++) {
                        int row = j0 + mt * 16 + s + arow;
                        uint32_t off = (uint32_t)(row * 128 + (((2 * k4 + ach) ^ (row & 7)) << 4));
                        ldsm4(ah[mt], ahb + off);
                        ldsm4(al[mt], alb + off);
                    }
                    uint32_t bh[4], bl[4];
                    {
                        uint32_t boff = (uint32_t)(brow * 128 + (((2 * k4 + bch) ^ (brow & 7)) << 4));
                        ldsm4(bh, bhb + boff);
                        ldsm4(bl, bhb + 4096 + boff);
                    }
                    #pragma unroll
                    for (int mt = 0; mt < 2; mt++)
                        #pragma unroll
                        for (int nt = 0; nt < 2; nt++) {
                            mma16816(acc[mt][nt], ah[mt], bh + nt * 2);  // xh*wh
                            mma16816(acc[mt][nt], ah[mt], bl + nt * 2);  // xh*wl
                            mma16816(acc[mt][nt], al[mt], bh + nt * 2);  // xl*wh
                        }
                }
            }
        }

        // Epilogue: direct fragment stores (32B-sector coalesced per quarter-warp)
        #pragma unroll
        for (int mt = 0; mt < 2; mt++)
            #pragma unroll
            for (int nt = 0; nt < 2; nt++) {
                int px = j0 + mt * 16 + (lid >> 2);
                int ox = ox0 + px;
                int co = co0 + n0 + nt * 8 + 2 * (lid & 3);
                float* bp = out + ((size_t)co * OHH + oy) * OWW + ox;
                const size_t cs = (size_t)OHH * OWW;
                if (ox < OWW)     { bp[0] = acc[mt][nt][0]; bp[cs] = acc[mt][nt][1]; }
                if (ox + 8 < OWW) { bp[8] = acc[mt][nt][2]; bp[cs + 8] = acc[mt][nt][3]; }
            }
    }
}

// ---------------- launch ----------------
extern "C" void kernel_launch(void* const* d_in, const int* in_sizes, int n_in,
                              void* d_out, int out_size)
{
    const float* x = (const float*)d_in[0];
    const float* w = (const float*)d_in[1];
    if (n_in >= 2 && in_sizes[0] < in_sizes[1]) {
        x = (const float*)d_in[1];
        w = (const float*)d_in[0];
    }
    float* out = (float*)d_out;

    cudaFuncSetAttribute(convt_mma_kernel,
                         cudaFuncAttributeMaxDynamicSharedMemorySize, SMEM_SZ);

    prepass_kernel<<<dim3(WW / 64, HH), 512>>>(x);
    // 2 co-halves x 9 px-tiles x 38 bands of 27 rows (38*27 = 1026)
    convt_mma_kernel<<<dim3(COUT / 32, 9, OHH / BAND), 256, SMEM_SZ>>>(w, out);
}